// round 11
// baseline (speedup 1.0000x reference)
#include <cuda_runtime.h>
#include <cuda_fp16.h>
#include <cstdint>

#define B 16
#define CI 64
#define CO 64
#define HH 192
#define WW 192
#define KDY 4
#define HID 17
#define GROUPS 8
#define CPG 8
#define PLANE (HH*WW)
#define TEMPERATURE 30.0f
#define EPS 1e-5f
#define SLOPE 0.01f

// padded fp16 x: rows 0..193 (=gy+1), cols 0..199 (=gx+4), halo zero
#define WP 200
#define HP 194
#define PPLANE (HP*WP)

// conv tiling: 4 chunks of 16 ci
#define NCH 4
#define SXHB 9216                   // x tile: 288 px * 32B
#define SBHB 18432                  // filters: 9*2*64*16B
#define SBUF (SXHB+SBHB)            // 27648
#define SMEM_DYN (2*SBUF + 32)      // + 2 mbarriers

// ---- device scratch ----
__device__ float   g_ppart[B*4*36*16];
__device__ float   g_pooled[B][CI];
__device__ float   g_attn[B][KDY];
__device__ __align__(16) __half g_xh[(size_t)B*4*PPLANE*16];  // [b][cc][pgpix][ci16] swizzled
__device__ __align__(16) uint32_t g_fh[B*4*9*2*64*4];  // [b][cc][tap][khalf][n][k8]
__device__ float   g_stats[B][GROUPS][2];

__device__ __forceinline__ void mma16(float* c, const uint32_t* a, const uint32_t* b) {
    asm volatile(
        "mma.sync.aligned.m16n8k16.row.col.f32.f16.f16.f32 "
        "{%0,%1,%2,%3}, {%4,%5,%6,%7}, {%8,%9}, {%0,%1,%2,%3};"
        : "+f"(c[0]), "+f"(c[1]), "+f"(c[2]), "+f"(c[3])
        : "r"(a[0]), "r"(a[1]), "r"(a[2]), "r"(a[3]), "r"(b[0]), "r"(b[1]));
}
__device__ __forceinline__ void ldsm4(uint32_t* r, uint32_t addr) {
    asm volatile("ldmatrix.sync.aligned.m8n8.x4.shared.b16 {%0,%1,%2,%3}, [%4];"
                 : "=r"(r[0]), "=r"(r[1]), "=r"(r[2]), "=r"(r[3]) : "r"(addr));
}
__device__ __forceinline__ void bulk_cp(uint32_t dst, const void* src,
                                        uint32_t bytes, uint32_t mbar) {
    asm volatile(
        "cp.async.bulk.shared::cluster.global.mbarrier::complete_tx::bytes "
        "[%0], [%1], %2, [%3];"
        :: "r"(dst), "l"(src), "r"(bytes), "r"(mbar) : "memory");
}
__device__ __forceinline__ void mbar_init(uint32_t a, uint32_t c) {
    asm volatile("mbarrier.init.shared.b64 [%0], %1;" :: "r"(a), "r"(c) : "memory");
}
__device__ __forceinline__ void mbar_expect(uint32_t a, uint32_t bytes) {
    asm volatile("mbarrier.arrive.expect_tx.shared.b64 _, [%0], %1;"
                 :: "r"(a), "r"(bytes) : "memory");
}
__device__ __forceinline__ void mbar_wait(uint32_t a, uint32_t par) {
    asm volatile("{\n\t.reg .pred P;\n"
                 "WAIT_%=:\n\t"
                 "mbarrier.try_wait.parity.acquire.cta.shared::cta.b64 P, [%0], %1;\n\t"
                 "@!P bra WAIT_%=;\n\t}" :: "r"(a), "r"(par) : "memory");
}

// ============================================================
// K1: convert x -> padded swizzled fp16 [b][cc][pg][ci16] + pool partials
// ============================================================
__global__ void __launch_bounds__(256)
convert_pool_kernel(const float* __restrict__ x) {
    int b = blockIdx.z, cc = blockIdx.y, pb = blockIdx.x;
    int t = threadIdx.x;
    const float* xp = x + ((size_t)b*CI + cc*16)*PLANE + pb*1024;
    __half* outbase = g_xh + (size_t)(b*4+cc)*PPLANE*16;

    float s[16];
    #pragma unroll
    for (int i = 0; i < 16; i++) s[i] = 0.f;

    #pragma unroll
    for (int it = 0; it < 4; it++) {
        int p = it*256 + t;
        int pp = pb*1024 + p;
        int gy = pp / WW, gx = pp - gy*WW;
        int pg = (gy+1)*WP + gx + 4;
        uint32_t h2[8];
        #pragma unroll
        for (int ci = 0; ci < 16; ci += 2) {
            float v0 = xp[(size_t)ci*PLANE + p];
            float v1 = xp[(size_t)(ci+1)*PLANE + p];
            s[ci] += v0; s[ci+1] += v1;
            __half2 h = __floats2half2_rn(v0, v1);
            h2[ci>>1] = *(uint32_t*)&h;
        }
        int sw = (pg >> 2) & 1;
        uint4* o = (uint4*)(outbase + (size_t)pg*16);
        o[0 ^ sw] = make_uint4(h2[0], h2[1], h2[2], h2[3]);
        o[1 ^ sw] = make_uint4(h2[4], h2[5], h2[6], h2[7]);
    }
    __shared__ float red[8][16];
    #pragma unroll
    for (int o = 16; o > 0; o >>= 1)
        #pragma unroll
        for (int i = 0; i < 16; i++) s[i] += __shfl_down_sync(~0u, s[i], o);
    if ((t & 31) == 0)
        #pragma unroll
        for (int i = 0; i < 16; i++) red[t>>5][i] = s[i];
    __syncthreads();
    if (t < 16) {
        float tot = 0.f;
        #pragma unroll
        for (int w = 0; w < 8; w++) tot += red[w][t];
        g_ppart[(((b*4+cc)*36) + pb)*16 + t] = tot;
    }
}

// ============================================================
// K2a: finish pool + attention MLP + softmax; zero group stats
// ============================================================
__global__ void attn_kernel(const float* __restrict__ w1,
                            const float* __restrict__ w2,
                            const float* __restrict__ b2) {
    int t = threadIdx.x;
    if (t < B * GROUPS * 2) ((float*)g_stats)[t] = 0.f;
    #pragma unroll
    for (int j = 0; j < 4; j++) {
        int idx = t*4 + j;
        int b = idx >> 6, ci = idx & 63;
        int cc = ci >> 4, i = ci & 15;
        float a = 0.f;
        const float* pp = g_ppart + ((b*4+cc)*36)*16 + i;
        #pragma unroll 4
        for (int p = 0; p < 36; p++) a += pp[p*16];
        g_pooled[b][ci] = a / (float)PLANE;
    }
    __syncthreads();
    if (t < B) {
        float h[HID];
        #pragma unroll
        for (int j = 0; j < HID; j++) {
            float a = 0.f;
            #pragma unroll 8
            for (int c = 0; c < CI; c++) a += g_pooled[t][c] * w1[j*CI + c];
            h[j] = a > 0.f ? a : 0.f;
        }
        float sc[KDY];
        float m = -1e30f;
        #pragma unroll
        for (int k = 0; k < KDY; k++) {
            float a = b2[k];
            #pragma unroll
            for (int j = 0; j < HID; j++) a += h[j] * w2[k*HID + j];
            sc[k] = a / TEMPERATURE;
            m = fmaxf(m, sc[k]);
        }
        float se = 0.f;
        #pragma unroll
        for (int k = 0; k < KDY; k++) { sc[k] = expf(sc[k] - m); se += sc[k]; }
        #pragma unroll
        for (int k = 0; k < KDY; k++) g_attn[t][k] = sc[k] / se;
    }
}

// ============================================================
// K2b: filter synthesis -> n-major 16B rows for ldmatrix
// ============================================================
__global__ void filt_kernel(const float* __restrict__ W) {
    int idx = blockIdx.x * 256 + threadIdx.x;
    int k2    = idx & 3;
    int n     = (idx >> 2) & 63;
    int khalf = (idx >> 8) & 1;
    int tap   = (idx >> 9) % 9;
    int rest  = idx / 4608;
    int cc = rest & 3, b = rest >> 2;
    int ci0 = cc*16 + khalf*8 + 2*k2;
    const int ks = CO*CI*9;
    float a0 = g_attn[b][0], a1 = g_attn[b][1], a2 = g_attn[b][2], a3 = g_attn[b][3];
    int w0 = (n*CI + ci0)*9 + tap;
    int w1 = w0 + 9;
    float f0 = a0*W[w0] + a1*W[w0+ks] + a2*W[w0+2*ks] + a3*W[w0+3*ks];
    float f1 = a0*W[w1] + a1*W[w1+ks] + a2*W[w1+2*ks] + a3*W[w1+3*ks];
    __half2 h = __floats2half2_rn(f0, f1);
    g_fh[idx] = *(uint32_t*)&h;
}

// ============================================================
// K3: implicit-GEMM fp16 conv; bulk-copy staging + ldmatrix/mma
// with CROSS-TAP fragment double-buffering (3 CTAs/SM).
// ============================================================
__global__ void __launch_bounds__(256, 3)
conv_kernel(float* __restrict__ out) {
    extern __shared__ __align__(128) unsigned char dynsm[];
    const uint32_t smb = (uint32_t)__cvta_generic_to_shared(dynsm);
    const uint32_t mb0 = smb + 2*SBUF;

    const int tid = threadIdx.x;
    const int w = tid >> 5, lane = tid & 31;
    const int tig = lane & 3, grp = lane >> 2;
    const int nw = w >> 2, mw = w & 3;
    const int row_w = mw & 1, col32 = (mw >> 1) * 32;
    const int b  = blockIdx.z;
    const int y0 = blockIdx.y * 2;
    const int x0 = blockIdx.x * 64;

    const int pixoff  = ((lane >> 3) & 1) * 8 + (lane & 7);
    const int halfbit = (lane >> 4) & 1;
    const uint32_t blane = (((lane >> 3) & 1) << 10) +
                           (nw*32 + ((lane >> 4) & 1)*8 + (lane & 7)) * 16;

    float acc[2][4][4];
    #pragma unroll
    for (int mt = 0; mt < 2; mt++)
        #pragma unroll
        for (int nt = 0; nt < 4; nt++)
            #pragma unroll
            for (int r = 0; r < 4; r++) acc[mt][nt][r] = 0.f;

    if (tid == 0) { mbar_init(mb0, 1); mbar_init(mb0 + 8, 1); }
    __syncthreads();

    auto stage = [&](int cc, int buf) {   // single-thread
        uint32_t bar = mb0 + buf*8;
        mbar_expect(bar, SBUF);
        bulk_cp(smb + buf*SBUF + SXHB,
                g_fh + (size_t)(b*4+cc)*4608, SBHB, bar);
        const __half* xs = g_xh +
            ((size_t)(b*4+cc)*PPLANE + (size_t)y0*WP + x0)*16;
        #pragma unroll
        for (int r = 0; r < 4; r++)
            bulk_cp(smb + buf*SBUF + r*2304, xs + (size_t)r*WP*16, 2304, bar);
    };

    auto compute = [&](int buf) {
        const uint32_t sxa = smb + buf*SBUF;
        const uint32_t sba = smb + buf*SBUF + SXHB + blane;
        uint32_t a[2][2][4], bf[2][8];
        // prime tap 0
        {
            const int P = row_w*72 + col32 + 3 + pixoff;
            #pragma unroll
            for (int mt = 0; mt < 2; mt++) {
                int pix = P + mt*16;
                ldsm4(a[0][mt], sxa + pix*32 + (((halfbit ^ (pix >> 2)) & 1) << 4));
            }
            ldsm4(bf[0],     sba);
            ldsm4(bf[0] + 4, sba + 256);
        }
        #pragma unroll
        for (int tap = 0; tap < 9; tap++) {
            const int cur = tap & 1, nxt = cur ^ 1;
            if (tap + 1 < 9) {   // prefetch tap+1 fragments before this tap's MMAs
                const int t1 = tap + 1;
                const int tg = t1 / 3, tloc = t1 - tg*3;
                const int P = (row_w + tg)*72 + col32 + 3 + tloc + pixoff;
                #pragma unroll
                for (int mt = 0; mt < 2; mt++) {
                    int pix = P + mt*16;
                    ldsm4(a[nxt][mt],
                          sxa + pix*32 + (((halfbit ^ (pix >> 2)) & 1) << 4));
                }
                ldsm4(bf[nxt],     sba + t1*2048);
                ldsm4(bf[nxt] + 4, sba + t1*2048 + 256);
            }
            #pragma unroll
            for (int mt = 0; mt < 2; mt++)
                #pragma unroll
                for (int nt = 0; nt < 4; nt++)
                    mma16(acc[mt][nt], a[cur][mt], &bf[cur][nt*2]);
        }
    };

    if (tid == 0) stage(0, 0);
    for (int ch = 0; ch < NCH; ch++) {
        if (tid == 0 && ch + 1 < NCH) stage(ch + 1, (ch + 1) & 1);
        mbar_wait(mb0 + (ch & 1)*8, (ch >> 1) & 1);
        compute(ch & 1);
        __syncthreads();   // buffer + mbarrier recycle safety
    }

    // ---- epilogue: store raw conv + fused GroupNorm partials ----
    float s[4], q[4];
    #pragma unroll
    for (int g = 0; g < 4; g++) { s[g] = 0.f; q[g] = 0.f; }

    float* ob = out + (size_t)b*CO*PLANE + (y0 + row_w)*WW;
    #pragma unroll
    for (int mt = 0; mt < 2; mt++) {
        #pragma unroll
        for (int nt = 0; nt < 4; nt++) {
            #pragma unroll
            for (int r = 0; r < 4; r++) {
                float v = acc[mt][nt][r];
                int gx = x0 + col32 + mt*16 + grp + ((r >> 1) << 3);
                int co = nw*32 + nt*8 + tig*2 + (r & 1);
                ob[co*PLANE + gx] = v;
                s[nt] += v;
                q[nt] += v*v;
            }
        }
    }
    #pragma unroll
    for (int o = 16; o > 0; o >>= 1) {
        #pragma unroll
        for (int g = 0; g < 4; g++) {
            s[g] += __shfl_down_sync(~0u, s[g], o);
            q[g] += __shfl_down_sync(~0u, q[g], o);
        }
    }
    if (lane == 0) {
        #pragma unroll
        for (int g = 0; g < 4; g++) {
            atomicAdd(&g_stats[b][nw*4 + g][0], s[g]);
            atomicAdd(&g_stats[b][nw*4 + g][1], q[g]);
        }
    }
}

// ============================================================
// K4: in-place GroupNorm + affine + LeakyReLU
// ============================================================
__global__ void norm_kernel(float* __restrict__ out,
                            const float* __restrict__ gamma,
                            const float* __restrict__ beta) {
    int idx = blockIdx.x * 256 + threadIdx.x;
    const int PL4 = PLANE / 4;
    int clin = idx / PL4;
    int co = clin % CO;
    int b  = clin / CO;
    int g  = co >> 3;
    float s = g_stats[b][g][0], q = g_stats[b][g][1];
    const float invN = 1.f / (float)(CPG * PLANE);
    float mean = s * invN;
    float var  = q * invN - mean*mean;
    float rstd = rsqrtf(var + EPS);
    float ga = gamma[co], be = beta[co];
    float4 v = ((float4*)out)[idx];
    float* pv = (float*)&v;
    #pragma unroll
    for (int i = 0; i < 4; i++) {
        float yn = (pv[i] - mean) * rstd * ga + be;
        pv[i] = yn >= 0.f ? yn : SLOPE * yn;
    }
    ((float4*)out)[idx] = v;
}

// ============================================================
extern "C" void kernel_launch(void* const* d_in, const int* in_sizes, int n_in,
                              void* d_out, int out_size) {
    const float* x  = (const float*)d_in[0];
    const float* w1 = (const float*)d_in[1];
    const float* w2 = (const float*)d_in[2];
    const float* b2 = (const float*)d_in[3];
    const float* W  = (const float*)d_in[4];
    const float* ga = (const float*)d_in[5];
    const float* be = (const float*)d_in[6];
    float* out = (float*)d_out;

    cudaFuncSetAttribute(conv_kernel,
                         cudaFuncAttributeMaxDynamicSharedMemorySize, SMEM_DYN);

    convert_pool_kernel<<<dim3(36, 4, B), 256>>>(x);
    attn_kernel<<<1, 256>>>(w1, w2, b2);
    filt_kernel<<<(B*4*9*2*64*4)/256, 256>>>(W);
    conv_kernel<<<dim3(3, 96, B), 256, SMEM_DYN>>>(out);
    norm_kernel<<<(B*CO*PLANE/4)/256, 256>>>(out, ga, be);
}

// round 12
// speedup vs baseline: 1.4691x; 1.4691x over previous
#include <cuda_runtime.h>
#include <cuda_fp16.h>
#include <cstdint>

#define B 16
#define CI 64
#define CO 64
#define HH 192
#define WW 192
#define KDY 4
#define HID 17
#define GROUPS 8
#define CPG 8
#define PLANE (HH*WW)
#define TEMPERATURE 30.0f
#define EPS 1e-5f
#define SLOPE 0.01f

// padded fp16 x: rows 0..193 (=gy+1), cols 0..199 (=gx+4), halo zero
#define WP 200
#define HP 194
#define PPLANE (HP*WP)

// conv: 4 ci-chunks, 3 col tiles, filters resident per (b, n-half)
#define NCH 4
#define NTILE 3
#define NSTEP (NCH*NTILE)
#define SFB 36864                   // filters: 4cc*9tap*2kh*32n*16B
#define SXHB 13824                  // x tile: 6 rows * 72 px * 32B
#define SX0 SFB
#define SX1 (SFB + SXHB)
#define SMB (SFB + 2*SXHB)          // 64512: mbF, mbX0, mbX1
#define SMEM_DYN (SMB + 32)

// ---- device scratch ----
__device__ float   g_ppart[B*4*36*16];
__device__ float   g_pooled[B][CI];
__device__ float   g_attn[B][KDY];
__device__ __align__(16) __half g_xh[(size_t)B*4*PPLANE*16];  // [b][cc][pg][ci16] swizzled
__device__ __align__(16) uint32_t g_fh[B*2*4*9*2*32*4];  // [b][nh][cc][tap][kh][n32][k8]
__device__ float   g_stats[B][GROUPS][2];

__device__ __forceinline__ void mma16(float* c, const uint32_t* a, const uint32_t* b) {
    asm volatile(
        "mma.sync.aligned.m16n8k16.row.col.f32.f16.f16.f32 "
        "{%0,%1,%2,%3}, {%4,%5,%6,%7}, {%8,%9}, {%0,%1,%2,%3};"
        : "+f"(c[0]), "+f"(c[1]), "+f"(c[2]), "+f"(c[3])
        : "r"(a[0]), "r"(a[1]), "r"(a[2]), "r"(a[3]), "r"(b[0]), "r"(b[1]));
}
__device__ __forceinline__ void ldsm4(uint32_t* r, uint32_t addr) {
    asm volatile("ldmatrix.sync.aligned.m8n8.x4.shared.b16 {%0,%1,%2,%3}, [%4];"
                 : "=r"(r[0]), "=r"(r[1]), "=r"(r[2]), "=r"(r[3]) : "r"(addr));
}
__device__ __forceinline__ void bulk_cp(uint32_t dst, const void* src,
                                        uint32_t bytes, uint32_t mbar) {
    asm volatile(
        "cp.async.bulk.shared::cluster.global.mbarrier::complete_tx::bytes "
        "[%0], [%1], %2, [%3];"
        :: "r"(dst), "l"(src), "r"(bytes), "r"(mbar) : "memory");
}
__device__ __forceinline__ void mbar_init(uint32_t a, uint32_t c) {
    asm volatile("mbarrier.init.shared.b64 [%0], %1;" :: "r"(a), "r"(c) : "memory");
}
__device__ __forceinline__ void mbar_expect(uint32_t a, uint32_t bytes) {
    asm volatile("mbarrier.arrive.expect_tx.shared.b64 _, [%0], %1;"
                 :: "r"(a), "r"(bytes) : "memory");
}
__device__ __forceinline__ void mbar_wait(uint32_t a, uint32_t par) {
    asm volatile("{\n\t.reg .pred P;\n"
                 "WAIT_%=:\n\t"
                 "mbarrier.try_wait.parity.acquire.cta.shared::cta.b64 P, [%0], %1;\n\t"
                 "@!P bra WAIT_%=;\n\t}" :: "r"(a), "r"(par) : "memory");
}

// ============================================================
// K1: convert x -> padded swizzled fp16 [b][cc][pg][ci16] + pool partials
// ============================================================
__global__ void __launch_bounds__(256)
convert_pool_kernel(const float* __restrict__ x) {
    int b = blockIdx.z, cc = blockIdx.y, pb = blockIdx.x;
    int t = threadIdx.x;
    const float* xp = x + ((size_t)b*CI + cc*16)*PLANE + pb*1024;
    __half* outbase = g_xh + (size_t)(b*4+cc)*PPLANE*16;

    float s[16];
    #pragma unroll
    for (int i = 0; i < 16; i++) s[i] = 0.f;

    #pragma unroll
    for (int it = 0; it < 4; it++) {
        int p = it*256 + t;
        int pp = pb*1024 + p;
        int gy = pp / WW, gx = pp - gy*WW;
        int pg = (gy+1)*WP + gx + 4;
        uint32_t h2[8];
        #pragma unroll
        for (int ci = 0; ci < 16; ci += 2) {
            float v0 = xp[(size_t)ci*PLANE + p];
            float v1 = xp[(size_t)(ci+1)*PLANE + p];
            s[ci] += v0; s[ci+1] += v1;
            __half2 h = __floats2half2_rn(v0, v1);
            h2[ci>>1] = *(uint32_t*)&h;
        }
        int sw = (pg >> 2) & 1;
        uint4* o = (uint4*)(outbase + (size_t)pg*16);
        o[0 ^ sw] = make_uint4(h2[0], h2[1], h2[2], h2[3]);
        o[1 ^ sw] = make_uint4(h2[4], h2[5], h2[6], h2[7]);
    }
    __shared__ float red[8][16];
    #pragma unroll
    for (int o = 16; o > 0; o >>= 1)
        #pragma unroll
        for (int i = 0; i < 16; i++) s[i] += __shfl_down_sync(~0u, s[i], o);
    if ((t & 31) == 0)
        #pragma unroll
        for (int i = 0; i < 16; i++) red[t>>5][i] = s[i];
    __syncthreads();
    if (t < 16) {
        float tot = 0.f;
        #pragma unroll
        for (int w = 0; w < 8; w++) tot += red[w][t];
        g_ppart[(((b*4+cc)*36) + pb)*16 + t] = tot;
    }
}

// ============================================================
// K2a: finish pool + attention MLP + softmax; zero group stats
// ============================================================
__global__ void attn_kernel(const float* __restrict__ w1,
                            const float* __restrict__ w2,
                            const float* __restrict__ b2) {
    int t = threadIdx.x;
    if (t < B * GROUPS * 2) ((float*)g_stats)[t] = 0.f;
    #pragma unroll
    for (int j = 0; j < 4; j++) {
        int idx = t*4 + j;
        int b = idx >> 6, ci = idx & 63;
        int cc = ci >> 4, i = ci & 15;
        float a = 0.f;
        const float* pp = g_ppart + ((b*4+cc)*36)*16 + i;
        #pragma unroll 4
        for (int p = 0; p < 36; p++) a += pp[p*16];
        g_pooled[b][ci] = a / (float)PLANE;
    }
    __syncthreads();
    if (t < B) {
        float h[HID];
        #pragma unroll
        for (int j = 0; j < HID; j++) {
            float a = 0.f;
            #pragma unroll 8
            for (int c = 0; c < CI; c++) a += g_pooled[t][c] * w1[j*CI + c];
            h[j] = a > 0.f ? a : 0.f;
        }
        float sc[KDY];
        float m = -1e30f;
        #pragma unroll
        for (int k = 0; k < KDY; k++) {
            float a = b2[k];
            #pragma unroll
            for (int j = 0; j < HID; j++) a += h[j] * w2[k*HID + j];
            sc[k] = a / TEMPERATURE;
            m = fmaxf(m, sc[k]);
        }
        float se = 0.f;
        #pragma unroll
        for (int k = 0; k < KDY; k++) { sc[k] = expf(sc[k] - m); se += sc[k]; }
        #pragma unroll
        for (int k = 0; k < KDY; k++) g_attn[t][k] = sc[k] / se;
    }
}

// ============================================================
// K2b: filter synthesis -> [b][nh][cc][tap][kh][n32][k8]
// ============================================================
__global__ void filt_kernel(const float* __restrict__ W) {
    int idx = blockIdx.x * 256 + threadIdx.x;
    int k2  = idx & 3;
    int n   = (idx >> 2) & 31;
    int kh  = (idx >> 7) & 1;
    int t2  = idx >> 8;
    int tap = t2 % 9;
    int t3  = t2 / 9;
    int cc  = t3 & 3;
    int nh  = (t3 >> 2) & 1;
    int b   = t3 >> 3;
    int ng  = nh*32 + n;
    int ci0 = cc*16 + kh*8 + 2*k2;
    const int ks = CO*CI*9;
    float a0 = g_attn[b][0], a1 = g_attn[b][1], a2 = g_attn[b][2], a3 = g_attn[b][3];
    int w0 = (ng*CI + ci0)*9 + tap;
    int w1 = w0 + 9;
    float f0 = a0*W[w0] + a1*W[w0+ks] + a2*W[w0+2*ks] + a3*W[w0+3*ks];
    float f1 = a0*W[w1] + a1*W[w1+ks] + a2*W[w1+2*ks] + a3*W[w1+3*ks];
    __half2 h = __floats2half2_rn(f0, f1);
    g_fh[idx] = *(uint32_t*)&h;
}

// ============================================================
// K3: implicit-GEMM fp16 conv, filters RESIDENT in smem.
// CTA = (b, n-half 32co, 4 rows x 64 cols), persistent over 3
// col tiles x 4 ci-chunks. x tile (6 rows) double-buffered via
// cp.async.bulk; ldmatrix + mma.m16n8k16; fused GN partials.
// ============================================================
__global__ void __launch_bounds__(256, 3)
conv_kernel(float* __restrict__ out) {
    extern __shared__ __align__(128) unsigned char dynsm[];
    const uint32_t smb = (uint32_t)__cvta_generic_to_shared(dynsm);
    const uint32_t mbF = smb + SMB, mbX = smb + SMB + 8;

    const int tid = threadIdx.x;
    const int w = tid >> 5, lane = tid & 31;
    const int tig = lane & 3, grp = lane >> 2;
    const int row_w = w >> 1, col32 = (w & 1) * 32;   // 8 m-slots: 4 rows x 2 col-halves
    const int b  = blockIdx.z;
    const int nh = blockIdx.y;
    const int y0 = blockIdx.x * 4;

    const int pixoff  = ((lane >> 3) & 1) * 8 + (lane & 7);
    const int halfbit = (lane >> 4) & 1;
    const uint32_t blane = (((lane >> 3) & 1) << 9) +
                           (((lane >> 4) & 1)*8 + (lane & 7)) * 16;

    float acc[2][4][4];
    float s[4], q[4];
    #pragma unroll
    for (int g = 0; g < 4; g++) { s[g] = 0.f; q[g] = 0.f; }

    if (tid == 0) {
        mbar_init(mbF, 1); mbar_init(mbX, 1); mbar_init(mbX + 8, 1);
    }
    __syncthreads();

    const __half* xbase = g_xh;   // per-chunk base computed in stage
    auto stage_x = [&](int step, int buf) {   // single-thread
        int t = step >> 2, cc = step & 3;
        uint32_t bar = mbX + buf*8;
        mbar_expect(bar, SXHB);
        const __half* xs = g_xh +
            ((size_t)(b*4+cc)*PPLANE + (size_t)y0*WP + t*64)*16;
        #pragma unroll
        for (int r = 0; r < 6; r++)
            bulk_cp(smb + SX0 + buf*SXHB + r*2304, xs + (size_t)r*WP*16, 2304, bar);
    };

    if (tid == 0) {
        // filters: one-shot resident stage (4 x 9216B)
        mbar_expect(mbF, SFB);
        const uint32_t* fsrc = g_fh + (size_t)(b*2+nh)*9216;
        #pragma unroll
        for (int cc = 0; cc < 4; cc++)
            bulk_cp(smb + cc*9216, fsrc + cc*2304, 9216, mbF);
        stage_x(0, 0);
    }
    mbar_wait(mbF, 0);

    for (int step = 0; step < NSTEP; step++) {
        const int cc = step & 3, tile = step >> 2, buf = step & 1;
        if (tid == 0 && step + 1 < NSTEP) stage_x(step + 1, buf ^ 1);
        if (cc == 0) {
            #pragma unroll
            for (int mt = 0; mt < 2; mt++)
                #pragma unroll
                for (int nt = 0; nt < 4; nt++)
                    #pragma unroll
                    for (int r = 0; r < 4; r++) acc[mt][nt][r] = 0.f;
        }
        mbar_wait(mbX + buf*8, (step >> 1) & 1);

        // ---- compute chunk ----
        {
            const uint32_t sxa = smb + SX0 + buf*SXHB;
            const uint32_t sba = smb + cc*9216 + blane;
            #pragma unroll
            for (int tap = 0; tap < 9; tap++) {
                const int tg = tap / 3, tloc = tap - tg*3;
                const int P = (row_w + tg)*72 + col32 + 3 + tloc + pixoff;
                uint32_t a[2][4];
                #pragma unroll
                for (int mt = 0; mt < 2; mt++) {
                    int pix = P + mt*16;
                    ldsm4(a[mt], sxa + pix*32 + (((halfbit ^ (pix >> 2)) & 1) << 4));
                }
                uint32_t bfr[8];
                ldsm4(bfr,     sba + tap*1024);
                ldsm4(bfr + 4, sba + tap*1024 + 256);
                #pragma unroll
                for (int mt = 0; mt < 2; mt++)
                    #pragma unroll
                    for (int nt = 0; nt < 4; nt++)
                        mma16(acc[mt][nt], a[mt], &bfr[nt*2]);
            }
        }

        if (cc == 3) {   // epilogue for this tile
            float* ob = out + (size_t)b*CO*PLANE + (y0 + row_w)*WW;
            const int x0 = tile*64;
            #pragma unroll
            for (int mt = 0; mt < 2; mt++) {
                #pragma unroll
                for (int nt = 0; nt < 4; nt++) {
                    #pragma unroll
                    for (int r = 0; r < 4; r++) {
                        float v = acc[mt][nt][r];
                        int gx = x0 + col32 + mt*16 + grp + ((r >> 1) << 3);
                        int co = nh*32 + nt*8 + tig*2 + (r & 1);
                        ob[co*PLANE + gx] = v;
                        s[nt] += v;
                        q[nt] += v*v;
                    }
                }
            }
        }
        __syncthreads();   // x-buffer recycle + mbarrier phase safety
    }

    // ---- GN partial reduction (once, over all 3 tiles) ----
    #pragma unroll
    for (int o = 16; o > 0; o >>= 1) {
        #pragma unroll
        for (int g = 0; g < 4; g++) {
            s[g] += __shfl_down_sync(~0u, s[g], o);
            q[g] += __shfl_down_sync(~0u, q[g], o);
        }
    }
    if (lane == 0) {
        #pragma unroll
        for (int g = 0; g < 4; g++) {
            atomicAdd(&g_stats[b][nh*4 + g][0], s[g]);
            atomicAdd(&g_stats[b][nh*4 + g][1], q[g]);
        }
    }
}

// ============================================================
// K4: in-place GroupNorm + affine + LeakyReLU
// ============================================================
__global__ void norm_kernel(float* __restrict__ out,
                            const float* __restrict__ gamma,
                            const float* __restrict__ beta) {
    int idx = blockIdx.x * 256 + threadIdx.x;
    const int PL4 = PLANE / 4;
    int clin = idx / PL4;
    int co = clin % CO;
    int b  = clin / CO;
    int g  = co >> 3;
    float s = g_stats[b][g][0], q = g_stats[b][g][1];
    const float invN = 1.f / (float)(CPG * PLANE);
    float mean = s * invN;
    float var  = q * invN - mean*mean;
    float rstd = rsqrtf(var + EPS);
    float ga = gamma[co], be = beta[co];
    float4 v = ((float4*)out)[idx];
    float* pv = (float*)&v;
    #pragma unroll
    for (int i = 0; i < 4; i++) {
        float yn = (pv[i] - mean) * rstd * ga + be;
        pv[i] = yn >= 0.f ? yn : SLOPE * yn;
    }
    ((float4*)out)[idx] = v;
}

// ============================================================
extern "C" void kernel_launch(void* const* d_in, const int* in_sizes, int n_in,
                              void* d_out, int out_size) {
    const float* x  = (const float*)d_in[0];
    const float* w1 = (const float*)d_in[1];
    const float* w2 = (const float*)d_in[2];
    const float* b2 = (const float*)d_in[3];
    const float* W  = (const float*)d_in[4];
    const float* ga = (const float*)d_in[5];
    const float* be = (const float*)d_in[6];
    float* out = (float*)d_out;

    cudaFuncSetAttribute(conv_kernel,
                         cudaFuncAttributeMaxDynamicSharedMemorySize, SMEM_DYN);

    convert_pool_kernel<<<dim3(36, 4, B), 256>>>(x);
    attn_kernel<<<1, 256>>>(w1, w2, b2);
    filt_kernel<<<(B*2*4*9*2*32*4)/256, 256>>>(W);
    conv_kernel<<<dim3(48, 2, B), 256, SMEM_DYN>>>(out);
    norm_kernel<<<(B*CO*PLANE/4)/256, 256>>>(out, ga, be);
}

// round 13
// speedup vs baseline: 1.4804x; 1.0077x over previous
#include <cuda_runtime.h>
#include <cuda_fp16.h>
#include <cstdint>

#define B 16
#define CI 64
#define CO 64
#define HH 192
#define WW 192
#define KDY 4
#define HID 17
#define GROUPS 8
#define CPG 8
#define PLANE (HH*WW)
#define TEMPERATURE 30.0f
#define EPS 1e-5f
#define SLOPE 0.01f

// padded fp16 x: rows 0..193 (=gy+1), cols 0..199 (=gx+4), halo zero
#define WP 200
#define HP 194
#define PPLANE (HP*WP)

// conv: 4 ci-chunks, 3 col tiles, filters resident per (b, n-half)
#define NCH 4
#define NTILE 3
#define NSTEP (NCH*NTILE)
#define SFB 36864                   // filters: 4cc*9tap*2kh*32n*16B
#define SXHB 13824                  // x tile: 6 rows * 72 px * 32B
#define SX0 SFB
#define SMB (SFB + 2*SXHB)          // 64512: mbF, mbX0, mbX1, mbC0, mbC1
#define SMEM_DYN (SMB + 48)

// ---- device scratch ----
__device__ float   g_ppart[B*4*36*16];
__device__ float   g_pooled[B][CI];
__device__ float   g_attn[B][KDY];
__device__ __align__(16) __half g_xh[(size_t)B*4*PPLANE*16];  // [b][cc][pg][ci16] swizzled
__device__ __align__(16) uint32_t g_fh[B*2*4*9*2*32*4];  // [b][nh][cc][tap][kh][n32][k8]
__device__ float   g_stats[B][GROUPS][2];

__device__ __forceinline__ void mma16(float* c, const uint32_t* a, const uint32_t* b) {
    asm volatile(
        "mma.sync.aligned.m16n8k16.row.col.f32.f16.f16.f32 "
        "{%0,%1,%2,%3}, {%4,%5,%6,%7}, {%8,%9}, {%0,%1,%2,%3};"
        : "+f"(c[0]), "+f"(c[1]), "+f"(c[2]), "+f"(c[3])
        : "r"(a[0]), "r"(a[1]), "r"(a[2]), "r"(a[3]), "r"(b[0]), "r"(b[1]));
}
__device__ __forceinline__ void ldsm4(uint32_t* r, uint32_t addr) {
    asm volatile("ldmatrix.sync.aligned.m8n8.x4.shared.b16 {%0,%1,%2,%3}, [%4];"
                 : "=r"(r[0]), "=r"(r[1]), "=r"(r[2]), "=r"(r[3]) : "r"(addr));
}
__device__ __forceinline__ void bulk_cp(uint32_t dst, const void* src,
                                        uint32_t bytes, uint32_t mbar) {
    asm volatile(
        "cp.async.bulk.shared::cluster.global.mbarrier::complete_tx::bytes "
        "[%0], [%1], %2, [%3];"
        :: "r"(dst), "l"(src), "r"(bytes), "r"(mbar) : "memory");
}
__device__ __forceinline__ void mbar_init(uint32_t a, uint32_t c) {
    asm volatile("mbarrier.init.shared.b64 [%0], %1;" :: "r"(a), "r"(c) : "memory");
}
__device__ __forceinline__ void mbar_expect(uint32_t a, uint32_t bytes) {
    asm volatile("mbarrier.arrive.expect_tx.shared.b64 _, [%0], %1;"
                 :: "r"(a), "r"(bytes) : "memory");
}
__device__ __forceinline__ void mbar_arrive(uint32_t a) {
    asm volatile("mbarrier.arrive.shared.b64 _, [%0];" :: "r"(a) : "memory");
}
__device__ __forceinline__ void mbar_wait(uint32_t a, uint32_t par) {
    asm volatile("{\n\t.reg .pred P;\n"
                 "WAIT_%=:\n\t"
                 "mbarrier.try_wait.parity.acquire.cta.shared::cta.b64 P, [%0], %1;\n\t"
                 "@!P bra WAIT_%=;\n\t}" :: "r"(a), "r"(par) : "memory");
}

// ============================================================
// K1: convert x -> padded swizzled fp16 [b][cc][pg][ci16] + pool partials
// ============================================================
__global__ void __launch_bounds__(256)
convert_pool_kernel(const float* __restrict__ x) {
    int b = blockIdx.z, cc = blockIdx.y, pb = blockIdx.x;
    int t = threadIdx.x;
    const float* xp = x + ((size_t)b*CI + cc*16)*PLANE + pb*1024;
    __half* outbase = g_xh + (size_t)(b*4+cc)*PPLANE*16;

    float s[16];
    #pragma unroll
    for (int i = 0; i < 16; i++) s[i] = 0.f;

    #pragma unroll
    for (int it = 0; it < 4; it++) {
        int p = it*256 + t;
        int pp = pb*1024 + p;
        int gy = pp / WW, gx = pp - gy*WW;
        int pg = (gy+1)*WP + gx + 4;
        uint32_t h2[8];
        #pragma unroll
        for (int ci = 0; ci < 16; ci += 2) {
            float v0 = xp[(size_t)ci*PLANE + p];
            float v1 = xp[(size_t)(ci+1)*PLANE + p];
            s[ci] += v0; s[ci+1] += v1;
            __half2 h = __floats2half2_rn(v0, v1);
            h2[ci>>1] = *(uint32_t*)&h;
        }
        int sw = (pg >> 2) & 1;
        uint4* o = (uint4*)(outbase + (size_t)pg*16);
        o[0 ^ sw] = make_uint4(h2[0], h2[1], h2[2], h2[3]);
        o[1 ^ sw] = make_uint4(h2[4], h2[5], h2[6], h2[7]);
    }
    __shared__ float red[8][16];
    #pragma unroll
    for (int o = 16; o > 0; o >>= 1)
        #pragma unroll
        for (int i = 0; i < 16; i++) s[i] += __shfl_down_sync(~0u, s[i], o);
    if ((t & 31) == 0)
        #pragma unroll
        for (int i = 0; i < 16; i++) red[t>>5][i] = s[i];
    __syncthreads();
    if (t < 16) {
        float tot = 0.f;
        #pragma unroll
        for (int w = 0; w < 8; w++) tot += red[w][t];
        g_ppart[(((b*4+cc)*36) + pb)*16 + t] = tot;
    }
}

// ============================================================
// K2a: finish pool + attention MLP + softmax; zero group stats
// ============================================================
__global__ void attn_kernel(const float* __restrict__ w1,
                            const float* __restrict__ w2,
                            const float* __restrict__ b2) {
    int t = threadIdx.x;
    if (t < B * GROUPS * 2) ((float*)g_stats)[t] = 0.f;
    #pragma unroll
    for (int j = 0; j < 4; j++) {
        int idx = t*4 + j;
        int b = idx >> 6, ci = idx & 63;
        int cc = ci >> 4, i = ci & 15;
        float a = 0.f;
        const float* pp = g_ppart + ((b*4+cc)*36)*16 + i;
        #pragma unroll 4
        for (int p = 0; p < 36; p++) a += pp[p*16];
        g_pooled[b][ci] = a / (float)PLANE;
    }
    __syncthreads();
    if (t < B) {
        float h[HID];
        #pragma unroll
        for (int j = 0; j < HID; j++) {
            float a = 0.f;
            #pragma unroll 8
            for (int c = 0; c < CI; c++) a += g_pooled[t][c] * w1[j*CI + c];
            h[j] = a > 0.f ? a : 0.f;
        }
        float sc[KDY];
        float m = -1e30f;
        #pragma unroll
        for (int k = 0; k < KDY; k++) {
            float a = b2[k];
            #pragma unroll
            for (int j = 0; j < HID; j++) a += h[j] * w2[k*HID + j];
            sc[k] = a / TEMPERATURE;
            m = fmaxf(m, sc[k]);
        }
        float se = 0.f;
        #pragma unroll
        for (int k = 0; k < KDY; k++) { sc[k] = expf(sc[k] - m); se += sc[k]; }
        #pragma unroll
        for (int k = 0; k < KDY; k++) g_attn[t][k] = sc[k] / se;
    }
}

// ============================================================
// K2b: filter synthesis -> [b][nh][cc][tap][kh][n32][k8]
// ============================================================
__global__ void filt_kernel(const float* __restrict__ W) {
    int idx = blockIdx.x * 256 + threadIdx.x;
    int k2  = idx & 3;
    int n   = (idx >> 2) & 31;
    int kh  = (idx >> 7) & 1;
    int t2  = idx >> 8;
    int tap = t2 % 9;
    int t3  = t2 / 9;
    int cc  = t3 & 3;
    int nh  = (t3 >> 2) & 1;
    int b   = t3 >> 3;
    int ng  = nh*32 + n;
    int ci0 = cc*16 + kh*8 + 2*k2;
    const int ks = CO*CI*9;
    float a0 = g_attn[b][0], a1 = g_attn[b][1], a2 = g_attn[b][2], a3 = g_attn[b][3];
    int w0 = (ng*CI + ci0)*9 + tap;
    int w1 = w0 + 9;
    float f0 = a0*W[w0] + a1*W[w0+ks] + a2*W[w0+2*ks] + a3*W[w0+3*ks];
    float f1 = a0*W[w1] + a1*W[w1+ks] + a2*W[w1+2*ks] + a3*W[w1+3*ks];
    __half2 h = __floats2half2_rn(f0, f1);
    g_fh[idx] = *(uint32_t*)&h;
}

// ============================================================
// K3: implicit-GEMM fp16 conv, filters RESIDENT in smem.
// Warp-decoupled pipeline: per-buffer consumer mbarriers (count 8)
// replace per-step __syncthreads; depth-2 x prefetch.
// ============================================================
__global__ void __launch_bounds__(256, 3)
conv_kernel(float* __restrict__ out) {
    extern __shared__ __align__(128) unsigned char dynsm[];
    const uint32_t smb = (uint32_t)__cvta_generic_to_shared(dynsm);
    const uint32_t mbF = smb + SMB;
    const uint32_t mbX = smb + SMB + 8;    // [2]
    const uint32_t mbC = smb + SMB + 24;   // [2], count 8

    const int tid = threadIdx.x;
    const int w = tid >> 5, lane = tid & 31;
    const int tig = lane & 3, grp = lane >> 2;
    const int row_w = w >> 1, col32 = (w & 1) * 32;
    const int b  = blockIdx.z;
    const int nh = blockIdx.y;
    const int y0 = blockIdx.x * 4;

    const int pixoff  = ((lane >> 3) & 1) * 8 + (lane & 7);
    const int halfbit = (lane >> 4) & 1;
    const uint32_t blane = (((lane >> 3) & 1) << 9) +
                           (((lane >> 4) & 1)*8 + (lane & 7)) * 16;

    float acc[2][4][4];
    float s[4], q[4];
    #pragma unroll
    for (int g = 0; g < 4; g++) { s[g] = 0.f; q[g] = 0.f; }

    if (tid == 0) {
        mbar_init(mbF, 1);
        mbar_init(mbX, 1);     mbar_init(mbX + 8, 1);
        mbar_init(mbC, 8);     mbar_init(mbC + 8, 8);
    }
    __syncthreads();

    auto stage_x = [&](int step, int buf) {   // single-thread
        int t = step >> 2, cc = step & 3;
        uint32_t bar = mbX + buf*8;
        mbar_expect(bar, SXHB);
        const __half* xs = g_xh +
            ((size_t)(b*4+cc)*PPLANE + (size_t)y0*WP + t*64)*16;
        #pragma unroll
        for (int r = 0; r < 6; r++)
            bulk_cp(smb + SX0 + buf*SXHB + r*2304, xs + (size_t)r*WP*16, 2304, bar);
    };

    if (tid == 0) {
        mbar_expect(mbF, SFB);
        const uint32_t* fsrc = g_fh + (size_t)(b*2+nh)*9216;
        #pragma unroll
        for (int cc = 0; cc < 4; cc++)
            bulk_cp(smb + cc*9216, fsrc + cc*2304, 9216, mbF);
        stage_x(0, 0);
        stage_x(1, 1);       // depth-2 prefetch
    }
    mbar_wait(mbF, 0);

    for (int step = 0; step < NSTEP; step++) {
        const int cc = step & 3, tile = step >> 2, buf = step & 1;
        const int ph = (step >> 1) & 1;
        if (cc == 0) {
            #pragma unroll
            for (int mt = 0; mt < 2; mt++)
                #pragma unroll
                for (int nt = 0; nt < 4; nt++)
                    #pragma unroll
                    for (int r = 0; r < 4; r++) acc[mt][nt][r] = 0.f;
        }
        mbar_wait(mbX + buf*8, ph);

        // ---- compute chunk ----
        {
            const uint32_t sxa = smb + SX0 + buf*SXHB;
            const uint32_t sba = smb + cc*9216 + blane;
            #pragma unroll
            for (int tap = 0; tap < 9; tap++) {
                const int tg = tap / 3, tloc = tap - tg*3;
                const int P = (row_w + tg)*72 + col32 + 3 + tloc + pixoff;
                uint32_t a[2][4];
                #pragma unroll
                for (int mt = 0; mt < 2; mt++) {
                    int pix = P + mt*16;
                    ldsm4(a[mt], sxa + pix*32 + (((halfbit ^ (pix >> 2)) & 1) << 4));
                }
                uint32_t bfr[8];
                ldsm4(bfr,     sba + tap*1024);
                ldsm4(bfr + 4, sba + tap*1024 + 256);
                #pragma unroll
                for (int mt = 0; mt < 2; mt++)
                    #pragma unroll
                    for (int nt = 0; nt < 4; nt++)
                        mma16(acc[mt][nt], a[mt], &bfr[nt*2]);
            }
        }

        // done reading this buffer: consumer arrive (one lane per warp)
        if (lane == 0) mbar_arrive(mbC + buf*8);

        if (cc == 3) {   // tile epilogue (registers only; overlaps staging)
            float* ob = out + (size_t)b*CO*PLANE + (y0 + row_w)*WW;
            const int x0 = tile*64;
            #pragma unroll
            for (int mt = 0; mt < 2; mt++) {
                #pragma unroll
                for (int nt = 0; nt < 4; nt++) {
                    #pragma unroll
                    for (int r = 0; r < 4; r++) {
                        float v = acc[mt][nt][r];
                        int gx = x0 + col32 + mt*16 + grp + ((r >> 1) << 3);
                        int co = nh*32 + nt*8 + tig*2 + (r & 1);
                        ob[co*PLANE + gx] = v;
                        s[nt] += v;
                        q[nt] += v*v;
                    }
                }
            }
        }

        // producer: once all 8 warps released this buffer, restage it
        if (tid == 0 && step + 2 < NSTEP) {
            mbar_wait(mbC + buf*8, ph);
            stage_x(step + 2, buf);
        }
    }

    // ---- GN partial reduction (once, over all 3 tiles) ----
    #pragma unroll
    for (int o = 16; o > 0; o >>= 1) {
        #pragma unroll
        for (int g = 0; g < 4; g++) {
            s[g] += __shfl_down_sync(~0u, s[g], o);
            q[g] += __shfl_down_sync(~0u, q[g], o);
        }
    }
    if (lane == 0) {
        #pragma unroll
        for (int g = 0; g < 4; g++) {
            atomicAdd(&g_stats[b][nh*4 + g][0], s[g]);
            atomicAdd(&g_stats[b][nh*4 + g][1], q[g]);
        }
    }
}

// ============================================================
// K4: in-place GroupNorm + affine + LeakyReLU
// ============================================================
__global__ void norm_kernel(float* __restrict__ out,
                            const float* __restrict__ gamma,
                            const float* __restrict__ beta) {
    int idx = blockIdx.x * 256 + threadIdx.x;
    const int PL4 = PLANE / 4;
    int clin = idx / PL4;
    int co = clin % CO;
    int b  = clin / CO;
    int g  = co >> 3;
    float s = g_stats[b][g][0], q = g_stats[b][g][1];
    const float invN = 1.f / (float)(CPG * PLANE);
    float mean = s * invN;
    float var  = q * invN - mean*mean;
    float rstd = rsqrtf(var + EPS);
    float ga = gamma[co], be = beta[co];
    float4 v = ((float4*)out)[idx];
    float* pv = (float*)&v;
    #pragma unroll
    for (int i = 0; i < 4; i++) {
        float yn = (pv[i] - mean) * rstd * ga + be;
        pv[i] = yn >= 0.f ? yn : SLOPE * yn;
    }
    ((float4*)out)[idx] = v;
}

// ============================================================
extern "C" void kernel_launch(void* const* d_in, const int* in_sizes, int n_in,
                              void* d_out, int out_size) {
    const float* x  = (const float*)d_in[0];
    const float* w1 = (const float*)d_in[1];
    const float* w2 = (const float*)d_in[2];
    const float* b2 = (const float*)d_in[3];
    const float* W  = (const float*)d_in[4];
    const float* ga = (const float*)d_in[5];
    const float* be = (const float*)d_in[6];
    float* out = (float*)d_out;

    cudaFuncSetAttribute(conv_kernel,
                         cudaFuncAttributeMaxDynamicSharedMemorySize, SMEM_DYN);

    convert_pool_kernel<<<dim3(36, 4, B), 256>>>(x);
    attn_kernel<<<1, 256>>>(w1, w2, b2);
    filt_kernel<<<(B*2*4*9*2*32*4)/256, 256>>>(W);
    conv_kernel<<<dim3(48, 2, B), 256, SMEM_DYN>>>(out);
    norm_kernel<<<(B*CO*PLANE/4)/256, 256>>>(out, ga, be);
}

// round 14
// speedup vs baseline: 1.7790x; 1.2017x over previous
#include <cuda_runtime.h>
#include <cuda_fp16.h>
#include <cstdint>

#define B 16
#define CI 64
#define CO 64
#define HH 192
#define WW 192
#define KDY 4
#define HID 17
#define GROUPS 8
#define CPG 8
#define PLANE (HH*WW)
#define TEMPERATURE 30.0f
#define EPS 1e-5f
#define SLOPE 0.01f

// padded fp16 x: rows 0..193 (=gy+1), cols 0..199 (=gx+4), halo zero
#define WP 200
#define HP 194
#define PPLANE (HP*WP)

// conv: 4 ci-chunks, 3 col tiles, filters resident per (b, n-half)
#define NCH 4
#define NTILE 3
#define NSTEP (NCH*NTILE)
#define SFB 36864                   // filters: 4cc*9tap*2kh*32n*16B
#define SXHB 13824                  // x tile: 6 rows * 72 px * 32B
#define SX0 SFB
#define SMB (SFB + 2*SXHB)          // mbF, mbX0, mbX1, mbC0, mbC1
#define SMEM_DYN (SMB + 48)

// ---- device scratch ----
__device__ float   g_ppart[B*4*36*16];
__device__ __align__(16) __half g_xh[(size_t)B*4*PPLANE*16];  // [b][cc][pg][ci16] swizzled
__device__ __align__(16) uint32_t g_fh[B*2*4*9*2*32*4];  // [b][nh][cc][tap][kh][n32][k8]
__device__ __align__(16) __half g_yh[(size_t)B*CO*PLANE]; // raw conv out, fp16
__device__ float   g_stats[B][GROUPS][2];

__device__ __forceinline__ void mma16(float* c, const uint32_t* a, const uint32_t* b) {
    asm volatile(
        "mma.sync.aligned.m16n8k16.row.col.f32.f16.f16.f32 "
        "{%0,%1,%2,%3}, {%4,%5,%6,%7}, {%8,%9}, {%0,%1,%2,%3};"
        : "+f"(c[0]), "+f"(c[1]), "+f"(c[2]), "+f"(c[3])
        : "r"(a[0]), "r"(a[1]), "r"(a[2]), "r"(a[3]), "r"(b[0]), "r"(b[1]));
}
__device__ __forceinline__ void ldsm4(uint32_t* r, uint32_t addr) {
    asm volatile("ldmatrix.sync.aligned.m8n8.x4.shared.b16 {%0,%1,%2,%3}, [%4];"
                 : "=r"(r[0]), "=r"(r[1]), "=r"(r[2]), "=r"(r[3]) : "r"(addr));
}
__device__ __forceinline__ void bulk_cp(uint32_t dst, const void* src,
                                        uint32_t bytes, uint32_t mbar) {
    asm volatile(
        "cp.async.bulk.shared::cluster.global.mbarrier::complete_tx::bytes "
        "[%0], [%1], %2, [%3];"
        :: "r"(dst), "l"(src), "r"(bytes), "r"(mbar) : "memory");
}
__device__ __forceinline__ void mbar_init(uint32_t a, uint32_t c) {
    asm volatile("mbarrier.init.shared.b64 [%0], %1;" :: "r"(a), "r"(c) : "memory");
}
__device__ __forceinline__ void mbar_expect(uint32_t a, uint32_t bytes) {
    asm volatile("mbarrier.arrive.expect_tx.shared.b64 _, [%0], %1;"
                 :: "r"(a), "r"(bytes) : "memory");
}
__device__ __forceinline__ void mbar_arrive(uint32_t a) {
    asm volatile("mbarrier.arrive.shared.b64 _, [%0];" :: "r"(a) : "memory");
}
__device__ __forceinline__ void mbar_wait(uint32_t a, uint32_t par) {
    asm volatile("{\n\t.reg .pred P;\n"
                 "WAIT_%=:\n\t"
                 "mbarrier.try_wait.parity.acquire.cta.shared::cta.b64 P, [%0], %1;\n\t"
                 "@!P bra WAIT_%=;\n\t}" :: "r"(a), "r"(par) : "memory");
}

// ============================================================
// K1: convert x -> padded swizzled fp16 [b][cc][pg][ci16] + pool partials
// ============================================================
__global__ void __launch_bounds__(256)
convert_pool_kernel(const float* __restrict__ x) {
    int b = blockIdx.z, cc = blockIdx.y, pb = blockIdx.x;
    int t = threadIdx.x;
    const float* xp = x + ((size_t)b*CI + cc*16)*PLANE + pb*1024;
    __half* outbase = g_xh + (size_t)(b*4+cc)*PPLANE*16;

    float s[16];
    #pragma unroll
    for (int i = 0; i < 16; i++) s[i] = 0.f;

    #pragma unroll
    for (int it = 0; it < 4; it++) {
        int p = it*256 + t;
        int pp = pb*1024 + p;
        int gy = pp / WW, gx = pp - gy*WW;
        int pg = (gy+1)*WP + gx + 4;
        uint32_t h2[8];
        #pragma unroll
        for (int ci = 0; ci < 16; ci += 2) {
            float v0 = xp[(size_t)ci*PLANE + p];
            float v1 = xp[(size_t)(ci+1)*PLANE + p];
            s[ci] += v0; s[ci+1] += v1;
            __half2 h = __floats2half2_rn(v0, v1);
            h2[ci>>1] = *(uint32_t*)&h;
        }
        int sw = (pg >> 2) & 1;
        uint4* o = (uint4*)(outbase + (size_t)pg*16);
        o[0 ^ sw] = make_uint4(h2[0], h2[1], h2[2], h2[3]);
        o[1 ^ sw] = make_uint4(h2[4], h2[5], h2[6], h2[7]);
    }
    __shared__ float red[8][16];
    #pragma unroll
    for (int o = 16; o > 0; o >>= 1)
        #pragma unroll
        for (int i = 0; i < 16; i++) s[i] += __shfl_down_sync(~0u, s[i], o);
    if ((t & 31) == 0)
        #pragma unroll
        for (int i = 0; i < 16; i++) red[t>>5][i] = s[i];
    __syncthreads();
    if (t < 16) {
        float tot = 0.f;
        #pragma unroll
        for (int w = 0; w < 8; w++) tot += red[w][t];
        g_ppart[(((b*4+cc)*36) + pb)*16 + t] = tot;
    }
}

// ============================================================
// K2: fused attention + filter synthesis.
// Each block's 256 outputs share one sample b -> block computes
// the tiny attn MLP + softmax redundantly from pool partials.
// Block 0 also zeroes g_stats (filt completes before conv).
// Output layout: [b][nh][cc][tap][kh][n32][k8]
// ============================================================
__global__ void __launch_bounds__(256)
filt_kernel(const float* __restrict__ W,
            const float* __restrict__ w1,
            const float* __restrict__ w2,
            const float* __restrict__ b2) {
    __shared__ float sp[CI];
    __shared__ float sh[HID];
    __shared__ float sa[KDY];

    int t = threadIdx.x;
    int idx = blockIdx.x * 256 + t;
    int b = blockIdx.x / 72;          // 294912/16/256 = 72 blocks per b

    if (blockIdx.x == 0) ((float*)g_stats)[t] = 0.f;

    // pooled means for this b
    if (t < 64) {
        int cc = t >> 4, i = t & 15;
        float a = 0.f;
        const float* pp = g_ppart + ((b*4+cc)*36)*16 + i;
        #pragma unroll 4
        for (int p = 0; p < 36; p++) a += pp[p*16];
        sp[t] = a / (float)PLANE;
    }
    __syncthreads();
    if (t < HID) {
        float a = 0.f;
        #pragma unroll 8
        for (int c = 0; c < CI; c++) a += sp[c] * w1[t*CI + c];
        sh[t] = a > 0.f ? a : 0.f;
    }
    __syncthreads();
    if (t < KDY) {
        float a = b2[t];
        #pragma unroll
        for (int j = 0; j < HID; j++) a += sh[j] * w2[t*HID + j];
        sa[t] = a / TEMPERATURE;
    }
    __syncthreads();
    if (t == 0) {
        float m = fmaxf(fmaxf(sa[0], sa[1]), fmaxf(sa[2], sa[3]));
        float e0 = expf(sa[0]-m), e1 = expf(sa[1]-m),
              e2 = expf(sa[2]-m), e3 = expf(sa[3]-m);
        float inv = 1.f / (e0+e1+e2+e3);
        sa[0] = e0*inv; sa[1] = e1*inv; sa[2] = e2*inv; sa[3] = e3*inv;
    }
    __syncthreads();

    // filter element
    int k2  = idx & 3;
    int n   = (idx >> 2) & 31;
    int kh  = (idx >> 7) & 1;
    int t2  = idx >> 8;
    int tap = t2 % 9;
    int t3  = t2 / 9;
    int cc  = t3 & 3;
    int nh  = (t3 >> 2) & 1;
    int ng  = nh*32 + n;
    int ci0 = cc*16 + kh*8 + 2*k2;
    const int ks = CO*CI*9;
    float a0 = sa[0], a1 = sa[1], a2 = sa[2], a3 = sa[3];
    int w0 = (ng*CI + ci0)*9 + tap;
    int w1i = w0 + 9;
    float f0 = a0*W[w0]  + a1*W[w0+ks]  + a2*W[w0+2*ks]  + a3*W[w0+3*ks];
    float f1 = a0*W[w1i] + a1*W[w1i+ks] + a2*W[w1i+2*ks] + a3*W[w1i+3*ks];
    __half2 h = __floats2half2_rn(f0, f1);
    g_fh[idx] = *(uint32_t*)&h;
}

// ============================================================
// K3: implicit-GEMM fp16 conv, filters RESIDENT in smem.
// Warp-decoupled pipeline; raw y written as fp16 to g_yh (L2-res).
// ============================================================
__global__ void __launch_bounds__(256, 3)
conv_kernel() {
    extern __shared__ __align__(128) unsigned char dynsm[];
    const uint32_t smb = (uint32_t)__cvta_generic_to_shared(dynsm);
    const uint32_t mbF = smb + SMB;
    const uint32_t mbX = smb + SMB + 8;    // [2]
    const uint32_t mbC = smb + SMB + 24;   // [2], count 8

    const int tid = threadIdx.x;
    const int w = tid >> 5, lane = tid & 31;
    const int tig = lane & 3, grp = lane >> 2;
    const int row_w = w >> 1, col32 = (w & 1) * 32;
    const int b  = blockIdx.z;
    const int nh = blockIdx.y;
    const int y0 = blockIdx.x * 4;

    const int pixoff  = ((lane >> 3) & 1) * 8 + (lane & 7);
    const int halfbit = (lane >> 4) & 1;
    const uint32_t blane = (((lane >> 3) & 1) << 9) +
                           (((lane >> 4) & 1)*8 + (lane & 7)) * 16;

    float acc[2][4][4];
    float s[4], q[4];
    #pragma unroll
    for (int g = 0; g < 4; g++) { s[g] = 0.f; q[g] = 0.f; }

    if (tid == 0) {
        mbar_init(mbF, 1);
        mbar_init(mbX, 1);     mbar_init(mbX + 8, 1);
        mbar_init(mbC, 8);     mbar_init(mbC + 8, 8);
    }
    __syncthreads();

    auto stage_x = [&](int step, int buf) {   // single-thread
        int t = step >> 2, cc = step & 3;
        uint32_t bar = mbX + buf*8;
        mbar_expect(bar, SXHB);
        const __half* xs = g_xh +
            ((size_t)(b*4+cc)*PPLANE + (size_t)y0*WP + t*64)*16;
        #pragma unroll
        for (int r = 0; r < 6; r++)
            bulk_cp(smb + SX0 + buf*SXHB + r*2304, xs + (size_t)r*WP*16, 2304, bar);
    };

    if (tid == 0) {
        mbar_expect(mbF, SFB);
        const uint32_t* fsrc = g_fh + (size_t)(b*2+nh)*9216;
        #pragma unroll
        for (int cc = 0; cc < 4; cc++)
            bulk_cp(smb + cc*9216, fsrc + cc*2304, 9216, mbF);
        stage_x(0, 0);
        stage_x(1, 1);       // depth-2 prefetch
    }
    mbar_wait(mbF, 0);

    for (int step = 0; step < NSTEP; step++) {
        const int cc = step & 3, tile = step >> 2, buf = step & 1;
        const int ph = (step >> 1) & 1;
        if (cc == 0) {
            #pragma unroll
            for (int mt = 0; mt < 2; mt++)
                #pragma unroll
                for (int nt = 0; nt < 4; nt++)
                    #pragma unroll
                    for (int r = 0; r < 4; r++) acc[mt][nt][r] = 0.f;
        }
        mbar_wait(mbX + buf*8, ph);

        // ---- compute chunk ----
        {
            const uint32_t sxa = smb + SX0 + buf*SXHB;
            const uint32_t sba = smb + cc*9216 + blane;
            #pragma unroll
            for (int tap = 0; tap < 9; tap++) {
                const int tg = tap / 3, tloc = tap - tg*3;
                const int P = (row_w + tg)*72 + col32 + 3 + tloc + pixoff;
                uint32_t a[2][4];
                #pragma unroll
                for (int mt = 0; mt < 2; mt++) {
                    int pix = P + mt*16;
                    ldsm4(a[mt], sxa + pix*32 + (((halfbit ^ (pix >> 2)) & 1) << 4));
                }
                uint32_t bfr[8];
                ldsm4(bfr,     sba + tap*1024);
                ldsm4(bfr + 4, sba + tap*1024 + 256);
                #pragma unroll
                for (int mt = 0; mt < 2; mt++)
                    #pragma unroll
                    for (int nt = 0; nt < 4; nt++)
                        mma16(acc[mt][nt], a[mt], &bfr[nt*2]);
            }
        }

        // done reading this buffer: consumer arrive (one lane per warp)
        if (lane == 0) mbar_arrive(mbC + buf*8);

        if (cc == 3) {   // tile epilogue: fp16 raw y + GN partials
            __half* ob = g_yh + (size_t)b*CO*PLANE + (y0 + row_w)*WW;
            const int x0 = tile*64;
            #pragma unroll
            for (int mt = 0; mt < 2; mt++) {
                #pragma unroll
                for (int nt = 0; nt < 4; nt++) {
                    #pragma unroll
                    for (int r = 0; r < 4; r++) {
                        float v = acc[mt][nt][r];
                        int gx = x0 + col32 + mt*16 + grp + ((r >> 1) << 3);
                        int co = nh*32 + nt*8 + tig*2 + (r & 1);
                        ob[co*PLANE + gx] = __float2half_rn(v);
                        s[nt] += v;
                        q[nt] += v*v;
                    }
                }
            }
        }

        // producer: once all 8 warps released this buffer, restage it
        if (tid == 0 && step + 2 < NSTEP) {
            mbar_wait(mbC + buf*8, ph);
            stage_x(step + 2, buf);
        }
    }

    // ---- GN partial reduction (once, over all 3 tiles) ----
    #pragma unroll
    for (int o = 16; o > 0; o >>= 1) {
        #pragma unroll
        for (int g = 0; g < 4; g++) {
            s[g] += __shfl_down_sync(~0u, s[g], o);
            q[g] += __shfl_down_sync(~0u, q[g], o);
        }
    }
    if (lane == 0) {
        #pragma unroll
        for (int g = 0; g < 4; g++) {
            atomicAdd(&g_stats[b][nh*4 + g][0], s[g]);
            atomicAdd(&g_stats[b][nh*4 + g][1], q[g]);
        }
    }
}

// ============================================================
// K4: GroupNorm + affine + LeakyReLU, fp16 in -> fp32 out
// ============================================================
__global__ void __launch_bounds__(256)
norm_kernel(float* __restrict__ out,
            const float* __restrict__ gamma,
            const float* __restrict__ beta) {
    int idx = blockIdx.x * 256 + threadIdx.x;   // 8-px unit
    const int PL8 = PLANE / 8;
    int clin = idx / PL8;
    int r    = idx - clin*PL8;
    int co = clin & 63;
    int b  = clin >> 6;
    int g  = co >> 3;
    float s = g_stats[b][g][0], q = g_stats[b][g][1];
    const float invN = 1.f / (float)(CPG * PLANE);
    float mean = s * invN;
    float var  = q * invN - mean*mean;
    float rstd = rsqrtf(var + EPS);
    float ga = gamma[co] * rstd, be = beta[co] - mean*ga;

    uint4 v = ((const uint4*)(g_yh + (size_t)clin*PLANE))[r];
    float4 o0, o1;
    float* po = (float*)&o0;
    const uint32_t* pv = (const uint32_t*)&v;
    #pragma unroll
    for (int i = 0; i < 4; i++) {
        __half2 h = *(const __half2*)&pv[i];
        float2 f = __half22float2(h);
        float y0 = f.x * ga + be;
        float y1 = f.y * ga + be;
        ((float*)&o0)[(2*i) & 3 | ((i>>1)<<2) ? 0 : 0] = 0; // placeholder removed below
    }
    // unpack cleanly
    {
        __half2 h0 = *(const __half2*)&pv[0];
        __half2 h1 = *(const __half2*)&pv[1];
        __half2 h2 = *(const __half2*)&pv[2];
        __half2 h3 = *(const __half2*)&pv[3];
        float2 f0 = __half22float2(h0), f1 = __half22float2(h1);
        float2 f2 = __half22float2(h2), f3 = __half22float2(h3);
        float y;
        y = f0.x*ga + be; o0.x = y >= 0.f ? y : SLOPE*y;
        y = f0.y*ga + be; o0.y = y >= 0.f ? y : SLOPE*y;
        y = f1.x*ga + be; o0.z = y >= 0.f ? y : SLOPE*y;
        y = f1.y*ga + be; o0.w = y >= 0.f ? y : SLOPE*y;
        y = f2.x*ga + be; o1.x = y >= 0.f ? y : SLOPE*y;
        y = f2.y*ga + be; o1.y = y >= 0.f ? y : SLOPE*y;
        y = f3.x*ga + be; o1.z = y >= 0.f ? y : SLOPE*y;
        y = f3.y*ga + be; o1.w = y >= 0.f ? y : SLOPE*y;
    }
    float4* op = (float4*)(out + (size_t)clin*PLANE) + r*2;
    op[0] = o0;
    op[1] = o1;
}

// ============================================================
extern "C" void kernel_launch(void* const* d_in, const int* in_sizes, int n_in,
                              void* d_out, int out_size) {
    const float* x  = (const float*)d_in[0];
    const float* w1 = (const float*)d_in[1];
    const float* w2 = (const float*)d_in[2];
    const float* b2 = (const float*)d_in[3];
    const float* W  = (const float*)d_in[4];
    const float* ga = (const float*)d_in[5];
    const float* be = (const float*)d_in[6];
    float* out = (float*)d_out;

    cudaFuncSetAttribute(conv_kernel,
                         cudaFuncAttributeMaxDynamicSharedMemorySize, SMEM_DYN);

    convert_pool_kernel<<<dim3(36, 4, B), 256>>>(x);
    filt_kernel<<<(B*2*4*9*2*32*4)/256, 256>>>(W, w1, w2, b2);
    conv_kernel<<<dim3(48, 2, B), 256, SMEM_DYN>>>();
    norm_kernel<<<(B*CO*PLANE/8)/256, 256>>>(out, ga, be);
}